// round 4
// baseline (speedup 1.0000x reference)
#include <cuda_runtime.h>
#include <math.h>

#define Nd    128
#define SLICE (Nd * Nd)          // 16384
#define VOL   (Nd * Nd * Nd)     // 2097152
#define NVOLS 8                  // 2 batches * 4 classes

// Accumulators + scratch (allocation-free rule: __device__ globals)
__device__ double g_S1[NVOLS];
__device__ double g_S2[NVOLS];
__device__ double g_Num[NVOLS];
__device__ double g_Den[NVOLS];
__device__ float  g_Mean[NVOLS];
__device__ float  g_scr[(size_t)NVOLS * VOL];   // 64 MiB scratch (blur intermediate)

// Gaussian taps: exp(-x^2 / (2*5^2)), x = -4..4 (NOT normalized, matches reference)
__constant__ float Gc[9] = {
    0.72614903f, 0.83527021f, 0.92311635f, 0.98019867f, 1.0f,
    0.98019867f, 0.92311635f, 0.83527021f, 0.72614903f
};

// Block-wide reduce of two floats -> double atomics (works for 128 or 512 thread blocks)
__device__ __forceinline__ void blockReduceAtomic(float a, float b, double* dA, double* dB) {
    const int tid  = threadIdx.x + threadIdx.y * blockDim.x;
    const int lane = tid & 31;
    const int wid  = tid >> 5;
    #pragma unroll
    for (int off = 16; off; off >>= 1) {
        a += __shfl_down_sync(0xffffffffu, a, off);
        b += __shfl_down_sync(0xffffffffu, b, off);
    }
    __shared__ float sa[16], sb[16];
    if (lane == 0) { sa[wid] = a; sb[wid] = b; }
    __syncthreads();
    if (tid == 0) {
        const int nw = (blockDim.x * blockDim.y) >> 5;
        double A = 0.0, B = 0.0;
        for (int i = 0; i < nw; ++i) { A += (double)sa[i]; B += (double)sb[i]; }
        atomicAdd(dA, A);
        atomicAdd(dB, B);
    }
}

__global__ void k_init() {
    const int i = threadIdx.x;
    if (i < NVOLS) { g_S1[i] = 0.0; g_S2[i] = 0.0; g_Num[i] = 0.0; g_Den[i] = 0.0; }
}

// Pass 1: blur along W (contiguous axis) labels -> g_scr, fused with
// per-(batch,class) sums S1 = sum(p*in), S2 = sum(p).
// Grid: (NVOLS, 1024). blockIdx.x = volume (fast-varying -> the 4 classes of a
// batch touch the same `inputs` rows back-to-back -> L2 reuse of inputs).
__global__ void k_pass1(const float* __restrict__ labels, const float* __restrict__ inputs) {
    const int iv   = blockIdx.x;           // 0..7 = b*4 + k
    const int rowg = blockIdx.y;           // 0..1023, each covers 16 rows of 128
    const int w    = threadIdx.x;          // 0..127
    __shared__ float s[Nd + 8];
    if (w < 4)      s[w]     = 0.f;        // left zero halo
    if (w >= Nd-4)  s[w + 8] = 0.f;        // right zero halo
    const size_t rbase = (size_t)rowg * 16 * Nd;
    const float* Lv = labels + (size_t)iv * VOL + rbase;
    const float* Iv = inputs + (size_t)(iv >> 2) * VOL + rbase;
    float*       Ov = g_scr  + (size_t)iv * VOL + rbase;
    float sumP = 0.f, sumPI = 0.f;
    for (int r = 0; r < 16; ++r) {
        const int off = r * Nd + w;
        const float p   = Lv[off];
        const float vin = Iv[off];
        __syncthreads();
        s[w + 4] = p;
        __syncthreads();
        float acc = 0.f;
        #pragma unroll
        for (int j = 0; j < 9; ++j) acc += Gc[j] * s[w + j];
        Ov[off] = acc;
        sumP  += p;
        sumPI += p * vin;
    }
    blockReduceAtomic(sumPI, sumP, &g_S1[iv], &g_S2[iv]);
}

__global__ void k_means() {
    const int i = threadIdx.x;
    if (i < NVOLS) {
        // class_mean = (S1/V) / (S2/V + 1e-5) = S1 / (S2 + 1e-5*V)
        g_Mean[i] = (float)(g_S1[i] / (g_S2[i] + 1e-5 * (double)VOL));
    }
}

// Pass 2: blur along H, in-place in g_scr. Rolling 9-tap register window per
// thread; each element read exactly once, reads/writes coalesced across w.
__global__ void k_pass2() {
    const int d  = blockIdx.x;     // 0..127
    const int iv = blockIdx.y;     // 0..7
    const int w  = threadIdx.x;    // 0..127
    float* base = g_scr + (size_t)iv * VOL + (size_t)d * SLICE;
    float win[9];
    #pragma unroll
    for (int k = 0; k < 4; ++k) win[k] = 0.f;           // h = -4..-1 (zero pad)
    #pragma unroll
    for (int k = 0; k < 4; ++k) win[4 + k] = base[k * Nd + w];  // h = 0..3
    for (int h = 0; h < Nd; ++h) {
        win[8] = (h + 4 < Nd) ? base[(h + 4) * Nd + w] : 0.f;
        float acc = 0.f;
        #pragma unroll
        for (int j = 0; j < 9; ++j) acc += Gc[j] * win[j];
        base[h * Nd + w] = acc;    // safe in-place: written after h+4 was read
        #pragma unroll
        for (int k = 0; k < 8; ++k) win[k] = win[k + 1];
    }
}

// Pass 3: blur along D (rolling window) FUSED with the weight computation and
// the num/den reductions, using self-adjointness of the blur:
//   num_k = sum( blur(p) * p * w ),  den_k = sum( blur(p) * w ),
//   w = exp(-((in - mean)^2)^2).
// Grid: (NVOLS, 32, 2), block (128, 4). blockIdx.x = iv fast-varying -> the 4
// classes of a batch stream the same inputs region concurrently -> L2 reuse.
__global__ void k_pass3(const float* __restrict__ labels, const float* __restrict__ inputs) {
    const int iv = blockIdx.x;                                   // 0..7
    const int h  = blockIdx.y * blockDim.y + threadIdx.y;        // 0..127
    const int d0 = blockIdx.z * 64;                              // 0 or 64
    const int w  = threadIdx.x;                                  // 0..127
    const float mean = g_Mean[iv];
    const float* S  = g_scr  + (size_t)iv * VOL;
    const float* Lv = labels + (size_t)iv * VOL;
    const float* Iv = inputs + (size_t)(iv >> 2) * VOL;
    const int hw = h * Nd + w;
    float win[9];
    #pragma unroll
    for (int k = 0; k < 8; ++k) {
        const int d = d0 - 4 + k;
        win[k] = (d >= 0) ? S[(size_t)d * SLICE + hw] : 0.f;
    }
    float numA = 0.f, denA = 0.f;
    for (int d = d0; d < d0 + 64; ++d) {
        win[8] = (d + 4 < Nd) ? S[(size_t)(d + 4) * SLICE + hw] : 0.f;
        float bp = 0.f;
        #pragma unroll
        for (int j = 0; j < 9; ++j) bp += Gc[j] * win[j];
        const size_t idx = (size_t)d * SLICE + hw;
        const float p   = Lv[idx];
        const float vin = Iv[idx];
        float df = vin - mean;
        df *= df;
        const float wgt = expf(-df * df);
        numA += bp * p * wgt;
        denA += bp * wgt;
        #pragma unroll
        for (int k = 0; k < 8; ++k) win[k] = win[k + 1];
    }
    blockReduceAtomic(numA, denA, &g_Num[iv], &g_Den[iv]);
}

__global__ void k_final(float* __restrict__ out) {
    if (threadIdx.x == 0) {
        double loss = 0.0;
        for (int k = 0; k < 4; ++k) {
            const double nn = g_Num[k] + g_Num[k + 4];
            const double dd = g_Den[k] + g_Den[k + 4];
            loss += fabs(nn / (dd + 1e-6));
        }
        out[0] = (float)(4.0 - loss);
    }
}

extern "C" void kernel_launch(void* const* d_in, const int* in_sizes, int n_in,
                              void* d_out, int out_size) {
    const float* labels = (const float*)d_in[0];
    const float* inputs = (const float*)d_in[1];
    if (n_in >= 2 && in_sizes[0] < in_sizes[1]) {  // labels is the bigger tensor
        labels = (const float*)d_in[1];
        inputs = (const float*)d_in[0];
    }
    k_init<<<1, 32>>>();
    k_pass1<<<dim3(NVOLS, 1024), 128>>>(labels, inputs);
    k_means<<<1, 32>>>();
    k_pass2<<<dim3(Nd, NVOLS), 128>>>();
    k_pass3<<<dim3(NVOLS, 32, 2), dim3(128, 4)>>>(labels, inputs);
    k_final<<<1, 32>>>((float*)d_out);
    (void)out_size;
}